// round 14
// baseline (speedup 1.0000x reference)
#include <cuda_runtime.h>
#include <cuda_fp16.h>

#define Wd 1280
#define WV 320                 // float4 per row
#define WH2 (WV * 2)           // half2 per row (640)
#define Hd 720
#define NPV (Hd * WV)          // float4 per plane
#define NPH2 (Hd * WH2)        // half2 per plane
#define PLANES 48
#define NH2 (PLANES * NPH2)    // half2 per tensor

// Single-chain fp16 scratch (d = hq - lq chain)
__device__ __half2 g_bufA[NH2];  // low2(d)
__device__ __half2 g_bufB[NH2];  // low4(d)

__device__ __forceinline__ int iclamp(int v, int lo, int hi) {
    return v < lo ? lo : (v > hi ? hi : v);
}
__device__ __forceinline__ float4 splat4(float v) { return make_float4(v, v, v, v); }

__device__ __forceinline__ float4 ldh4(const __half2* p) {
    uint2 u = *(const uint2*)p;
    __half2 a = *(__half2*)&u.x, b = *(__half2*)&u.y;
    float2 fa = __half22float2(a), fb = __half22float2(b);
    return make_float4(fa.x, fa.y, fb.x, fb.y);
}
__device__ __forceinline__ void sth4(__half2* p, float4 v) {
    __half2 a = __floats2half2_rn(v.x, v.y), b = __floats2half2_rn(v.z, v.w);
    uint2 u;
    u.x = *(unsigned*)&a; u.y = *(unsigned*)&b;
    *(uint2*)p = u;
}
// packed fp16 quad in 2 regs
__device__ __forceinline__ uint2 pack4(float4 v) {
    __half2 a = __floats2half2_rn(v.x, v.y), b = __floats2half2_rn(v.z, v.w);
    uint2 u;
    u.x = *(unsigned*)&a; u.y = *(unsigned*)&b;
    return u;
}
__device__ __forceinline__ float4 unpack4(uint2 u) {
    __half2 a = *(__half2*)&u.x, b = *(__half2*)&u.y;
    float2 fa = __half22float2(a), fb = __half22float2(b);
    return make_float4(fa.x, fa.y, fb.x, fb.y);
}
__device__ __forceinline__ uint2 ldh4r(const __half2* p) { return *(const uint2*)p; }

__device__ __forceinline__ float4 fsub(float4 a, float4 b) {
    return make_float4(a.x - b.x, a.y - b.y, a.z - b.z, a.w - b.w);
}

// 0.25*(a+d) + 0.5*b
__device__ __forceinline__ float4 vmix(float4 a, float4 b, float4 d) {
    float4 o;
    o.x = fmaf(0.25f, a.x + d.x, 0.5f * b.x);
    o.y = fmaf(0.25f, a.y + d.y, 0.5f * b.y);
    o.z = fmaf(0.25f, a.z + d.z, 0.5f * b.z);
    o.w = fmaf(0.25f, a.w + d.w, 0.5f * b.w);
    return o;
}

// Fused two-level tap: [1,2,3,4,3,2,1]/16
__device__ __forceinline__ float t7(float a0, float a1, float a2, float a3,
                                    float a4, float a5, float a6) {
    return fmaf(0.25f, a3, fmaf(0.1875f, a2 + a4,
           fmaf(0.125f, a1 + a5, 0.0625f * (a0 + a6))));
}
__device__ __forceinline__ float4 f7(float4 a0, float4 a1, float4 a2, float4 a3,
                                     float4 a4, float4 a5, float4 a6) {
    float4 o;
    o.x = t7(a0.x, a1.x, a2.x, a3.x, a4.x, a5.x, a6.x);
    o.y = t7(a0.y, a1.y, a2.y, a3.y, a4.y, a5.y, a6.y);
    o.z = t7(a0.z, a1.z, a2.z, a3.z, a4.z, a5.z, a6.z);
    o.w = t7(a0.w, a1.w, a2.w, a3.w, a4.w, a5.w, a6.w);
    return o;
}

// ── Exact border vertical on the diff of two fp32 sources (levels 1+2) ──
__device__ __forceinline__ float4 dval(const float4* __restrict__ s1,
                                       const float4* __restrict__ s2, int q, int c) {
    return fsub(s1[(size_t)q * WV + c], s2[(size_t)q * WV + c]);
}
__device__ __forceinline__ float4 v1tap_d(const float4* __restrict__ s1,
                                          const float4* __restrict__ s2, int q, int c) {
    q = iclamp(q, 0, Hd - 1);
    int ym = iclamp(q - 1, 0, Hd - 1), yp = iclamp(q + 1, 0, Hd - 1);
    return vmix(dval(s1, s2, ym, c), dval(s1, s2, q, c), dval(s1, s2, yp, c));
}
__device__ __forceinline__ float4 vv_exact_d(const float4* __restrict__ s1,
                                             const float4* __restrict__ s2, int y, int c) {
    return vmix(v1tap_d(s1, s2, y - 2, c), v1tap_d(s1, s2, y, c),
                v1tap_d(s1, s2, y + 2, c));
}

// ── Exact border vertical, fp16 source, R=4 fused pair (levels 3+4) ──
__device__ __forceinline__ float4 v1tap_h4(const __half2* __restrict__ src, int q, int c2) {
    q = iclamp(q, 0, Hd - 1);
    int ym = iclamp(q - 4, 0, Hd - 1), yp = iclamp(q + 4, 0, Hd - 1);
    return vmix(ldh4(src + (size_t)ym * WH2 + c2), ldh4(src + (size_t)q * WH2 + c2),
                ldh4(src + (size_t)yp * WH2 + c2));
}
__device__ __forceinline__ float4 vv_exact_h4(const __half2* __restrict__ src, int y, int c2) {
    return vmix(v1tap_h4(src, y - 8, c2), v1tap_h4(src, y, c2), v1tap_h4(src, y + 8, c2));
}

// ── Exact border horizontal (full-width fp32 smem row, AB) ──
template <int RS>
__device__ __forceinline__ float hh_lh(const float* row, int q) {
    q = iclamp(q, 0, Wd - 1);
    return fmaf(0.25f, row[iclamp(q - RS, 0, Wd - 1)] + row[iclamp(q + RS, 0, Wd - 1)],
                0.5f * row[q]);
}
template <int RS>
__device__ __forceinline__ float hh_exact_px(const float* row, int p) {
    return fmaf(0.25f, hh_lh<RS>(row, iclamp(p - 2 * RS, 0, Wd - 1)) +
                        hh_lh<RS>(row, iclamp(p + 2 * RS, 0, Wd - 1)),
                0.5f * hh_lh<RS>(row, p));
}

// ── Exact border horizontal for CD tile rows, fp16 smem row ──
__device__ __forceinline__ float hh_lh4h(const __half* rh, int q, int off) {
    q = iclamp(q, 0, Wd - 1);
    return fmaf(0.25f, __half2float(rh[iclamp(q - 4, 0, Wd - 1) + off]) +
                        __half2float(rh[iclamp(q + 4, 0, Wd - 1) + off]),
                0.5f * __half2float(rh[q + off]));
}
__device__ __forceinline__ float hh_ex4h(const __half* rh, int p, int off) {
    return fmaf(0.25f, hh_lh4h(rh, iclamp(p - 8, 0, Wd - 1), off) +
                        hh_lh4h(rh, iclamp(p + 8, 0, Wd - 1), off),
                0.5f * hh_lh4h(rh, p, off));
}

// ───── Kernel A: d = hq - lq, levels 1+2 fused, 24-row band, 9-deep window ─────
#define TH_A 24
#define NB_A (Hd / TH_A)   // 30
__global__ void __launch_bounds__(320, 3)
levelAB(const float4* __restrict__ hq4, const float4* __restrict__ lq4,
        __half2* __restrict__ dstD) {
    __shared__ float4 s[8 * WV];  // 40 KB
    const int c = threadIdx.x;
    const int y0 = blockIdx.x * TH_A;
    const int z = blockIdx.y;
    const float4* s1 = hq4 + (size_t)z * NPV;
    const float4* s2 = lq4 + (size_t)z * NPV;
    __half2* dst = dstD + (size_t)z * NPH2;

    const bool interior = (y0 >= 3) && (y0 + TH_A - 1 + 3 < Hd);
    const float4* p1 = s1 + (size_t)(y0 - 3) * WV + c;
    const float4* p2 = s2 + (size_t)(y0 - 3) * WV + c;
    uint2 w[9];  // fp16-packed window, prefetch distance 3 (18 regs)
    if (interior) {
        #pragma unroll
        for (int i = 0; i < 9; i++)
            w[i] = pack4(fsub(__ldg(p1 + (size_t)i * WV), __ldg(p2 + (size_t)i * WV)));
    }

    #pragma unroll
    for (int ch = 0; ch < 3; ch++) {
        if (interior) {
            #pragma unroll
            for (int r = 0; r < 8; r++) {
                const int rr = ch * 8 + r;   // 0..23; taps rows rr..rr+6
                s[r * WV + c] = f7(unpack4(w[rr % 9]), unpack4(w[(rr + 1) % 9]),
                                   unpack4(w[(rr + 2) % 9]), unpack4(w[(rr + 3) % 9]),
                                   unpack4(w[(rr + 4) % 9]), unpack4(w[(rr + 5) % 9]),
                                   unpack4(w[(rr + 6) % 9]));
                if (rr + 9 <= TH_A + 5)      // rows 0..TH_A+5 exist in the band
                    w[rr % 9] = pack4(fsub(__ldg(p1 + (size_t)(9 + rr) * WV),
                                           __ldg(p2 + (size_t)(9 + rr) * WV)));
            }
        } else {
            #pragma unroll
            for (int r = 0; r < 8; r++)
                s[r * WV + c] = vv_exact_d(s1, s2, y0 + ch * 8 + r, c);
        }
        __syncthreads();
        #pragma unroll
        for (int r = 0; r < 8; r++) {
            const float4* row = s + r * WV;
            float4 o;
            if (c >= 1 && c <= WV - 2) {
                float4 L = row[c - 1], C = row[c], R = row[c + 1];
                o.x = t7(L.y, L.z, L.w, C.x, C.y, C.z, C.w);
                o.y = t7(L.z, L.w, C.x, C.y, C.z, C.w, R.x);
                o.z = t7(L.w, C.x, C.y, C.z, C.w, R.x, R.y);
                o.w = t7(C.x, C.y, C.z, C.w, R.x, R.y, R.z);
            } else {
                const float* rf = (const float*)row;
                int p0 = c * 4;
                o.x = hh_exact_px<1>(rf, p0);
                o.y = hh_exact_px<1>(rf, p0 + 1);
                o.z = hh_exact_px<1>(rf, p0 + 2);
                o.w = hh_exact_px<1>(rf, p0 + 3);
            }
            sth4(dst + (size_t)(y0 + ch * 8 + r) * WH2 + 2 * c, o);
        }
        __syncthreads();
    }
}

// ───── Kernel B: levels 3+4 fused on d, residue chains, fp16 smem + packed window ─────
#define TH_B 48
#define NB_B (Hd / TH_B)   // 15
#define TW_B 160
#define WT_B 166
#define SWH (WT_B * 2)     // half2 per smem row (332)
__global__ void __launch_bounds__(672)
levelCD(const __half2* __restrict__ srcD, __half2* __restrict__ dstD) {
    extern __shared__ __half2 vb[];  // [24][SWH] fp16 = 31872 B
    const int c = threadIdx.x;      // 0..167 (166..167 idle in vertical)
    const int rho = threadIdx.y;    // residue 0..3
    const int tx0 = blockIdx.x * TW_B;
    const int y0 = blockIdx.y * TH_B;
    const int z = blockIdx.z;
    const __half2* src = srcD + (size_t)z * NPH2;
    __half2* dst = dstD + (size_t)z * NPH2;

    const int jv = tx0 - 3 + c;
    const int c2 = 2 * iclamp(jv, 0, WV - 1);
    const bool interior = (y0 >= 12) && (y0 + 3 + 44 + 12 < Hd);  // uniform
    const __half2* p = src + (size_t)(y0 + rho - 12) * WH2 + c2;
    uint2 w[7];  // raw fp16 window
    if (interior && c < WT_B) {
        #pragma unroll
        for (int i = 0; i < 7; i++) w[i] = ldh4r(p + (size_t)(4 * i) * WH2);
    }

    #pragma unroll
    for (int ch = 0; ch < 2; ch++) {
        if (c < WT_B) {
            if (interior) {
                #pragma unroll
                for (int k = 0; k < 6; k++) {
                    const int kk = ch * 6 + k;
                    sth4(&vb[(rho + 4 * k) * SWH + 2 * c],
                         f7(unpack4(w[kk % 7]), unpack4(w[(kk + 1) % 7]),
                            unpack4(w[(kk + 2) % 7]), unpack4(w[(kk + 3) % 7]),
                            unpack4(w[(kk + 4) % 7]), unpack4(w[(kk + 5) % 7]),
                            unpack4(w[(kk + 6) % 7])));
                    if (kk < 11) w[kk % 7] = ldh4r(p + (size_t)(4 * (7 + kk)) * WH2);
                }
            } else {
                #pragma unroll
                for (int k = 0; k < 6; k++)
                    sth4(&vb[(rho + 4 * k) * SWH + 2 * c],
                         vv_exact_h4(src, y0 + ch * 24 + rho + 4 * k, c2));
            }
        }
        __syncthreads();
        if (c >= 3 && c <= 162) {
            const int j = tx0 + c - 3;
            #pragma unroll
            for (int k = 0; k < 6; k++) {
                const int rr = ch * 24 + rho + 4 * k;
                const __half2* row = vb + (rho + 4 * k) * SWH;
                float4 o;
                if (j >= 3 && j <= WV - 4) {
                    o = f7(ldh4(row + 2 * (c - 3)), ldh4(row + 2 * (c - 2)),
                           ldh4(row + 2 * (c - 1)), ldh4(row + 2 * c),
                           ldh4(row + 2 * (c + 1)), ldh4(row + 2 * (c + 2)),
                           ldh4(row + 2 * (c + 3)));
                } else {
                    const __half* rh = (const __half*)row;
                    const int off = 12 - tx0 * 4;
                    const int p0 = j * 4;
                    o.x = hh_ex4h(rh, p0, off);
                    o.y = hh_ex4h(rh, p0 + 1, off);
                    o.z = hh_ex4h(rh, p0 + 2, off);
                    o.w = hh_ex4h(rh, p0 + 3, off);
                }
                sth4(dst + (size_t)(y0 + rr) * WH2 + 2 * j, o);
            }
        }
        __syncthreads();
    }
}

// ───── Kernel C: level 5 (R=16) direct (no smem, no syncs) + combine ─────
#define RF5 4
__global__ void __launch_bounds__(320)
final5(const __half2* __restrict__ lowD, const float4* __restrict__ hq4,
       float4* __restrict__ out) {
    const int c = threadIdx.x;
    const int y0 = blockIdx.x * RF5;
    const int z = blockIdx.y;
    const __half2* sD = lowD + (size_t)z * NPH2;
    const float4* hp = hq4 + (size_t)z * NPV;
    float4* op = out + (size_t)z * NPV;

    #pragma unroll
    for (int r = 0; r < RF5; r++) {
        const int y = y0 + r;
        const int ym = iclamp(y - 16, 0, Hd - 1);
        const int yp = iclamp(y + 16, 0, Hd - 1);
        const __half2* rm = sD + (size_t)ym * WH2;
        const __half2* rc = sD + (size_t)y * WH2;
        const __half2* rp = sD + (size_t)yp * WH2;

        const int cm = (c >= 4) ? (c - 4) : 0;
        const int cp = (c <= WV - 5) ? (c + 4) : (WV - 1);
        float4 Vc = vmix(ldh4(rm + 2 * c),  ldh4(rc + 2 * c),  ldh4(rp + 2 * c));
        float4 Vm = vmix(ldh4(rm + 2 * cm), ldh4(rc + 2 * cm), ldh4(rp + 2 * cm));
        float4 Vp = vmix(ldh4(rm + 2 * cp), ldh4(rc + 2 * cp), ldh4(rp + 2 * cp));
        if (c < 4) Vm = splat4(Vm.x);
        if (c > WV - 5) Vp = splat4(Vp.w);
        float4 lo = vmix(Vm, Vc, Vp);

        float4 h = __ldg(hp + (size_t)y * WV + c);
        float4 o;
        o.x = fminf(fmaxf(h.x - lo.x, -1.0f), 1.0f);
        o.y = fminf(fmaxf(h.y - lo.y, -1.0f), 1.0f);
        o.z = fminf(fmaxf(h.z - lo.z, -1.0f), 1.0f);
        o.w = fminf(fmaxf(h.w - lo.w, -1.0f), 1.0f);
        op[(size_t)y * WV + c] = o;
    }
}

extern "C" void kernel_launch(void* const* d_in, const int* in_sizes, int n_in,
                              void* d_out, int out_size) {
    const float4* hq = (const float4*)d_in[0];
    const float4* lq = (const float4*)d_in[1];
    float4* out = (float4*)d_out;

    __half2 *A, *B;
    cudaGetSymbolAddress((void**)&A, g_bufA);
    cudaGetSymbolAddress((void**)&B, g_bufB);

    const int smemB = 24 * SWH * sizeof(__half2);  // 31872
    cudaFuncSetAttribute(levelCD, cudaFuncAttributeMaxDynamicSharedMemorySize, smemB);

    // levels 1+2 on d = hq - lq: fp32 inputs -> A (low2(d), fp16)
    levelAB<<<dim3(NB_A, PLANES), dim3(320, 1)>>>(hq, lq, A);
    // levels 3+4: A -> B (low4(d), fp16)
    levelCD<<<dim3(WV / TW_B, NB_B, PLANES), dim3(168, 4), smemB>>>(A, B);
    // level 5 + combine: out = clip(hq - low5(d)), direct, syncless
    final5<<<dim3(Hd / RF5, PLANES), dim3(320, 1)>>>(B, hq, out);
}

// round 15
// speedup vs baseline: 1.0633x; 1.0633x over previous
#include <cuda_runtime.h>
#include <cuda_fp16.h>

#define Wd 1280
#define WV 320                 // float4 per row
#define WH2 (WV * 2)           // half2 per row (640)
#define Hd 720
#define NPV (Hd * WV)          // float4 per plane
#define NPH2 (Hd * WH2)        // half2 per plane
#define PLANES 48
#define NH2 (PLANES * NPH2)    // half2 per tensor

// Single-chain fp16 scratch (d = hq - lq chain)
__device__ __half2 g_bufA[NH2];  // low2(d)
__device__ __half2 g_bufB[NH2];  // low4(d)

__device__ __forceinline__ int iclamp(int v, int lo, int hi) {
    return v < lo ? lo : (v > hi ? hi : v);
}
__device__ __forceinline__ float4 splat4(float v) { return make_float4(v, v, v, v); }

__device__ __forceinline__ float4 ldh4(const __half2* p) {
    uint2 u = *(const uint2*)p;
    __half2 a = *(__half2*)&u.x, b = *(__half2*)&u.y;
    float2 fa = __half22float2(a), fb = __half22float2(b);
    return make_float4(fa.x, fa.y, fb.x, fb.y);
}
__device__ __forceinline__ void sth4(__half2* p, float4 v) {
    __half2 a = __floats2half2_rn(v.x, v.y), b = __floats2half2_rn(v.z, v.w);
    uint2 u;
    u.x = *(unsigned*)&a; u.y = *(unsigned*)&b;
    *(uint2*)p = u;
}
// packed fp16 quad in 2 regs
__device__ __forceinline__ uint2 pack4(float4 v) {
    __half2 a = __floats2half2_rn(v.x, v.y), b = __floats2half2_rn(v.z, v.w);
    uint2 u;
    u.x = *(unsigned*)&a; u.y = *(unsigned*)&b;
    return u;
}
__device__ __forceinline__ float4 unpack4(uint2 u) {
    __half2 a = *(__half2*)&u.x, b = *(__half2*)&u.y;
    float2 fa = __half22float2(a), fb = __half22float2(b);
    return make_float4(fa.x, fa.y, fb.x, fb.y);
}
__device__ __forceinline__ uint2 ldh4r(const __half2* p) { return *(const uint2*)p; }

__device__ __forceinline__ float4 fsub(float4 a, float4 b) {
    return make_float4(a.x - b.x, a.y - b.y, a.z - b.z, a.w - b.w);
}

// 0.25*(a+d) + 0.5*b
__device__ __forceinline__ float4 vmix(float4 a, float4 b, float4 d) {
    float4 o;
    o.x = fmaf(0.25f, a.x + d.x, 0.5f * b.x);
    o.y = fmaf(0.25f, a.y + d.y, 0.5f * b.y);
    o.z = fmaf(0.25f, a.z + d.z, 0.5f * b.z);
    o.w = fmaf(0.25f, a.w + d.w, 0.5f * b.w);
    return o;
}

// Fused two-level tap: [1,2,3,4,3,2,1]/16
__device__ __forceinline__ float t7(float a0, float a1, float a2, float a3,
                                    float a4, float a5, float a6) {
    return fmaf(0.25f, a3, fmaf(0.1875f, a2 + a4,
           fmaf(0.125f, a1 + a5, 0.0625f * (a0 + a6))));
}
__device__ __forceinline__ float4 f7(float4 a0, float4 a1, float4 a2, float4 a3,
                                     float4 a4, float4 a5, float4 a6) {
    float4 o;
    o.x = t7(a0.x, a1.x, a2.x, a3.x, a4.x, a5.x, a6.x);
    o.y = t7(a0.y, a1.y, a2.y, a3.y, a4.y, a5.y, a6.y);
    o.z = t7(a0.z, a1.z, a2.z, a3.z, a4.z, a5.z, a6.z);
    o.w = t7(a0.w, a1.w, a2.w, a3.w, a4.w, a5.w, a6.w);
    return o;
}

// ── Exact border vertical on the diff of two fp32 sources (levels 1+2) ──
__device__ __forceinline__ float4 dval(const float4* __restrict__ s1,
                                       const float4* __restrict__ s2, int q, int c) {
    return fsub(s1[(size_t)q * WV + c], s2[(size_t)q * WV + c]);
}
__device__ __forceinline__ float4 v1tap_d(const float4* __restrict__ s1,
                                          const float4* __restrict__ s2, int q, int c) {
    q = iclamp(q, 0, Hd - 1);
    int ym = iclamp(q - 1, 0, Hd - 1), yp = iclamp(q + 1, 0, Hd - 1);
    return vmix(dval(s1, s2, ym, c), dval(s1, s2, q, c), dval(s1, s2, yp, c));
}
__device__ __forceinline__ float4 vv_exact_d(const float4* __restrict__ s1,
                                             const float4* __restrict__ s2, int y, int c) {
    return vmix(v1tap_d(s1, s2, y - 2, c), v1tap_d(s1, s2, y, c),
                v1tap_d(s1, s2, y + 2, c));
}

// ── Exact border vertical, fp16 source, R=4 fused pair (levels 3+4) ──
__device__ __forceinline__ float4 v1tap_h4(const __half2* __restrict__ src, int q, int c2) {
    q = iclamp(q, 0, Hd - 1);
    int ym = iclamp(q - 4, 0, Hd - 1), yp = iclamp(q + 4, 0, Hd - 1);
    return vmix(ldh4(src + (size_t)ym * WH2 + c2), ldh4(src + (size_t)q * WH2 + c2),
                ldh4(src + (size_t)yp * WH2 + c2));
}
__device__ __forceinline__ float4 vv_exact_h4(const __half2* __restrict__ src, int y, int c2) {
    return vmix(v1tap_h4(src, y - 8, c2), v1tap_h4(src, y, c2), v1tap_h4(src, y + 8, c2));
}

// ── Exact border horizontal (full-width fp32 smem row, AB) ──
template <int RS>
__device__ __forceinline__ float hh_lh(const float* row, int q) {
    q = iclamp(q, 0, Wd - 1);
    return fmaf(0.25f, row[iclamp(q - RS, 0, Wd - 1)] + row[iclamp(q + RS, 0, Wd - 1)],
                0.5f * row[q]);
}
template <int RS>
__device__ __forceinline__ float hh_exact_px(const float* row, int p) {
    return fmaf(0.25f, hh_lh<RS>(row, iclamp(p - 2 * RS, 0, Wd - 1)) +
                        hh_lh<RS>(row, iclamp(p + 2 * RS, 0, Wd - 1)),
                0.5f * hh_lh<RS>(row, p));
}

// ── Exact border horizontal for CD tile rows, fp16 smem row ──
__device__ __forceinline__ float hh_lh4h(const __half* rh, int q, int off) {
    q = iclamp(q, 0, Wd - 1);
    return fmaf(0.25f, __half2float(rh[iclamp(q - 4, 0, Wd - 1) + off]) +
                        __half2float(rh[iclamp(q + 4, 0, Wd - 1) + off]),
                0.5f * __half2float(rh[q + off]));
}
__device__ __forceinline__ float hh_ex4h(const __half* rh, int p, int off) {
    return fmaf(0.25f, hh_lh4h(rh, iclamp(p - 8, 0, Wd - 1), off) +
                        hh_lh4h(rh, iclamp(p + 8, 0, Wd - 1), off),
                0.5f * hh_lh4h(rh, p, off));
}

// ───── Kernel A: d = hq - lq, levels 1+2 fused, 16-row band, 9-deep window ─────
#define TH_A 16
#define NB_A (Hd / TH_A)   // 45
__global__ void __launch_bounds__(320, 3)
levelAB(const float4* __restrict__ hq4, const float4* __restrict__ lq4,
        __half2* __restrict__ dstD) {
    __shared__ float4 s[8 * WV];  // 40 KB
    const int c = threadIdx.x;
    const int y0 = blockIdx.x * TH_A;
    const int z = blockIdx.y;
    const float4* s1 = hq4 + (size_t)z * NPV;
    const float4* s2 = lq4 + (size_t)z * NPV;
    __half2* dst = dstD + (size_t)z * NPH2;

    const bool interior = (y0 >= 3) && (y0 + TH_A - 1 + 3 < Hd);
    const float4* p1 = s1 + (size_t)(y0 - 3) * WV + c;
    const float4* p2 = s2 + (size_t)(y0 - 3) * WV + c;
    uint2 w[9];  // fp16-packed window, prefetch distance 3 (18 regs)
    if (interior) {
        #pragma unroll
        for (int i = 0; i < 9; i++)
            w[i] = pack4(fsub(__ldg(p1 + (size_t)i * WV), __ldg(p2 + (size_t)i * WV)));
    }

    #pragma unroll
    for (int ch = 0; ch < 2; ch++) {
        if (interior) {
            #pragma unroll
            for (int r = 0; r < 8; r++) {
                const int rr = ch * 8 + r;   // 0..15; taps rows rr..rr+6 of 0..21
                s[r * WV + c] = f7(unpack4(w[rr % 9]), unpack4(w[(rr + 1) % 9]),
                                   unpack4(w[(rr + 2) % 9]), unpack4(w[(rr + 3) % 9]),
                                   unpack4(w[(rr + 4) % 9]), unpack4(w[(rr + 5) % 9]),
                                   unpack4(w[(rr + 6) % 9]));
                if (rr + 9 <= TH_A + 5)      // band holds rows 0..TH_A+5
                    w[rr % 9] = pack4(fsub(__ldg(p1 + (size_t)(9 + rr) * WV),
                                           __ldg(p2 + (size_t)(9 + rr) * WV)));
            }
        } else {
            #pragma unroll
            for (int r = 0; r < 8; r++)
                s[r * WV + c] = vv_exact_d(s1, s2, y0 + ch * 8 + r, c);
        }
        __syncthreads();
        #pragma unroll
        for (int r = 0; r < 8; r++) {
            const float4* row = s + r * WV;
            float4 o;
            if (c >= 1 && c <= WV - 2) {
                float4 L = row[c - 1], C = row[c], R = row[c + 1];
                o.x = t7(L.y, L.z, L.w, C.x, C.y, C.z, C.w);
                o.y = t7(L.z, L.w, C.x, C.y, C.z, C.w, R.x);
                o.z = t7(L.w, C.x, C.y, C.z, C.w, R.x, R.y);
                o.w = t7(C.x, C.y, C.z, C.w, R.x, R.y, R.z);
            } else {
                const float* rf = (const float*)row;
                int p0 = c * 4;
                o.x = hh_exact_px<1>(rf, p0);
                o.y = hh_exact_px<1>(rf, p0 + 1);
                o.z = hh_exact_px<1>(rf, p0 + 2);
                o.w = hh_exact_px<1>(rf, p0 + 3);
            }
            sth4(dst + (size_t)(y0 + ch * 8 + r) * WH2 + 2 * c, o);
        }
        __syncthreads();
    }
}

// ───── Kernel B: levels 3+4 fused on d, residue chains, fp16 smem + packed window ─────
#define TH_B 48
#define NB_B (Hd / TH_B)   // 15
#define TW_B 160
#define WT_B 166
#define SWH (WT_B * 2)     // half2 per smem row (332)
__global__ void __launch_bounds__(672)
levelCD(const __half2* __restrict__ srcD, __half2* __restrict__ dstD) {
    extern __shared__ __half2 vb[];  // [24][SWH] fp16 = 31872 B
    const int c = threadIdx.x;      // 0..167 (166..167 idle in vertical)
    const int rho = threadIdx.y;    // residue 0..3
    const int tx0 = blockIdx.x * TW_B;
    const int y0 = blockIdx.y * TH_B;
    const int z = blockIdx.z;
    const __half2* src = srcD + (size_t)z * NPH2;
    __half2* dst = dstD + (size_t)z * NPH2;

    const int jv = tx0 - 3 + c;
    const int c2 = 2 * iclamp(jv, 0, WV - 1);
    const bool interior = (y0 >= 12) && (y0 + 3 + 44 + 12 < Hd);  // uniform
    const __half2* p = src + (size_t)(y0 + rho - 12) * WH2 + c2;
    uint2 w[7];  // raw fp16 window
    if (interior && c < WT_B) {
        #pragma unroll
        for (int i = 0; i < 7; i++) w[i] = ldh4r(p + (size_t)(4 * i) * WH2);
    }

    #pragma unroll
    for (int ch = 0; ch < 2; ch++) {
        if (c < WT_B) {
            if (interior) {
                #pragma unroll
                for (int k = 0; k < 6; k++) {
                    const int kk = ch * 6 + k;
                    sth4(&vb[(rho + 4 * k) * SWH + 2 * c],
                         f7(unpack4(w[kk % 7]), unpack4(w[(kk + 1) % 7]),
                            unpack4(w[(kk + 2) % 7]), unpack4(w[(kk + 3) % 7]),
                            unpack4(w[(kk + 4) % 7]), unpack4(w[(kk + 5) % 7]),
                            unpack4(w[(kk + 6) % 7])));
                    if (kk < 11) w[kk % 7] = ldh4r(p + (size_t)(4 * (7 + kk)) * WH2);
                }
            } else {
                #pragma unroll
                for (int k = 0; k < 6; k++)
                    sth4(&vb[(rho + 4 * k) * SWH + 2 * c],
                         vv_exact_h4(src, y0 + ch * 24 + rho + 4 * k, c2));
            }
        }
        __syncthreads();
        if (c >= 3 && c <= 162) {
            const int j = tx0 + c - 3;
            #pragma unroll
            for (int k = 0; k < 6; k++) {
                const int rr = ch * 24 + rho + 4 * k;
                const __half2* row = vb + (rho + 4 * k) * SWH;
                float4 o;
                if (j >= 3 && j <= WV - 4) {
                    o = f7(ldh4(row + 2 * (c - 3)), ldh4(row + 2 * (c - 2)),
                           ldh4(row + 2 * (c - 1)), ldh4(row + 2 * c),
                           ldh4(row + 2 * (c + 1)), ldh4(row + 2 * (c + 2)),
                           ldh4(row + 2 * (c + 3)));
                } else {
                    const __half* rh = (const __half*)row;
                    const int off = 12 - tx0 * 4;
                    const int p0 = j * 4;
                    o.x = hh_ex4h(rh, p0, off);
                    o.y = hh_ex4h(rh, p0 + 1, off);
                    o.z = hh_ex4h(rh, p0 + 2, off);
                    o.w = hh_ex4h(rh, p0 + 3, off);
                }
                sth4(dst + (size_t)(y0 + rr) * WH2 + 2 * j, o);
            }
        }
        __syncthreads();
    }
}

// ───── Kernel C: level 5 (R=16) direct (no smem, no syncs) + combine ─────
#define RF5 4
__global__ void __launch_bounds__(320)
final5(const __half2* __restrict__ lowD, const float4* __restrict__ hq4,
       float4* __restrict__ out) {
    const int c = threadIdx.x;
    const int y0 = blockIdx.x * RF5;
    const int z = blockIdx.y;
    const __half2* sD = lowD + (size_t)z * NPH2;
    const float4* hp = hq4 + (size_t)z * NPV;
    float4* op = out + (size_t)z * NPV;

    #pragma unroll
    for (int r = 0; r < RF5; r++) {
        const int y = y0 + r;
        const int ym = iclamp(y - 16, 0, Hd - 1);
        const int yp = iclamp(y + 16, 0, Hd - 1);
        const __half2* rm = sD + (size_t)ym * WH2;
        const __half2* rc = sD + (size_t)y * WH2;
        const __half2* rp = sD + (size_t)yp * WH2;

        const int cm = (c >= 4) ? (c - 4) : 0;
        const int cp = (c <= WV - 5) ? (c + 4) : (WV - 1);
        float4 Vc = vmix(ldh4(rm + 2 * c),  ldh4(rc + 2 * c),  ldh4(rp + 2 * c));
        float4 Vm = vmix(ldh4(rm + 2 * cm), ldh4(rc + 2 * cm), ldh4(rp + 2 * cm));
        float4 Vp = vmix(ldh4(rm + 2 * cp), ldh4(rc + 2 * cp), ldh4(rp + 2 * cp));
        if (c < 4) Vm = splat4(Vm.x);
        if (c > WV - 5) Vp = splat4(Vp.w);
        float4 lo = vmix(Vm, Vc, Vp);

        float4 h = __ldg(hp + (size_t)y * WV + c);
        float4 o;
        o.x = fminf(fmaxf(h.x - lo.x, -1.0f), 1.0f);
        o.y = fminf(fmaxf(h.y - lo.y, -1.0f), 1.0f);
        o.z = fminf(fmaxf(h.z - lo.z, -1.0f), 1.0f);
        o.w = fminf(fmaxf(h.w - lo.w, -1.0f), 1.0f);
        op[(size_t)y * WV + c] = o;
    }
}

extern "C" void kernel_launch(void* const* d_in, const int* in_sizes, int n_in,
                              void* d_out, int out_size) {
    const float4* hq = (const float4*)d_in[0];
    const float4* lq = (const float4*)d_in[1];
    float4* out = (float4*)d_out;

    __half2 *A, *B;
    cudaGetSymbolAddress((void**)&A, g_bufA);
    cudaGetSymbolAddress((void**)&B, g_bufB);

    const int smemB = 24 * SWH * sizeof(__half2);  // 31872
    cudaFuncSetAttribute(levelCD, cudaFuncAttributeMaxDynamicSharedMemorySize, smemB);

    // levels 1+2 on d = hq - lq: fp32 inputs -> A (low2(d), fp16)
    levelAB<<<dim3(NB_A, PLANES), dim3(320, 1)>>>(hq, lq, A);
    // levels 3+4: A -> B (low4(d), fp16)
    levelCD<<<dim3(WV / TW_B, NB_B, PLANES), dim3(168, 4), smemB>>>(A, B);
    // level 5 + combine: out = clip(hq - low5(d)), direct, syncless
    final5<<<dim3(Hd / RF5, PLANES), dim3(320, 1)>>>(B, hq, out);
}